// round 1
// baseline (speedup 1.0000x reference)
#include <cuda_runtime.h>
#include <cuda_bf16.h>

#define BB 8192
#define DD 512
#define W1 256          // phase-1 candidate window
#define BM 64
#define BN 64
#define BK 32

// -------- scratch (device globals; no allocation allowed) --------
__device__ float g_an[BB * DD];   // normalized img
__device__ float g_tn[BB * DD];   // normalized txt
__device__ float g_cn[BB * DD];   // normalized txt_cr
__device__ float g_sm[BB];        // diag(sim)     = <img_n, txt_n>
__device__ float g_smcr[BB];      // diag(sim_cr)  = <img_n, txtcr_n>
__device__ float g_mcr[BB];       // margin_cr per row
__device__ unsigned long long g_best[4][BB];  // (j<<32)|float_bits(loss), ~0 = none
__device__ int g_cnt[4];
__device__ int g_list[4][BB];

static __device__ __forceinline__ unsigned long long umin64(unsigned long long a,
                                                            unsigned long long b) {
    return a < b ? a : b;
}

// pass 0: sim rows     (A=img_n, B=txt_n,   diag=sm,    marg=margin)
// pass 1: sim cols     (A=txt_n, B=img_n,   diag=sm,    marg=margin)
// pass 2: sim_cr rows  (A=img_n, B=txtcr_n, diag=smcr,  marg=margin_cr)
// pass 3: sim_cr cols  (A=txtcr_n, B=img_n, diag=smcr,  marg=margin_cr)
static __device__ __forceinline__ void pass_ptrs(int pass, const float* margin,
                                                 const float*& A, const float*& Bm,
                                                 const float*& dg, const float*& mg) {
    switch (pass) {
        case 0: A = g_an; Bm = g_tn; dg = g_sm;   mg = margin; break;
        case 1: A = g_tn; Bm = g_an; dg = g_sm;   mg = margin; break;
        case 2: A = g_an; Bm = g_cn; dg = g_smcr; mg = g_mcr;  break;
        default:A = g_cn; Bm = g_an; dg = g_smcr; mg = g_mcr;  break;
    }
}

// -------- kernel 1: row-normalize, diag sims, margin_cr, state reset --------
__global__ __launch_bounds__(256) void prep_kernel(
    const float* __restrict__ img, const float* __restrict__ txt,
    const float* __restrict__ cr, const float* __restrict__ margin,
    const int* __restrict__ aflag) {
    int row = blockIdx.x * 8 + (threadIdx.x >> 5);
    int lane = threadIdx.x & 31;
    const float* pi = img + (size_t)row * DD;
    const float* pt = txt + (size_t)row * DD;
    const float* pc = cr + (size_t)row * DD;

    float vi[16], vt[16], vc[16];
    float sii = 0.f, stt = 0.f, scc = 0.f, sit = 0.f, sic = 0.f;
#pragma unroll
    for (int e = 0; e < 16; e++) {
        int idx = lane + 32 * e;
        vi[e] = pi[idx]; vt[e] = pt[idx]; vc[e] = pc[idx];
        sii += vi[e] * vi[e]; stt += vt[e] * vt[e]; scc += vc[e] * vc[e];
        sit += vi[e] * vt[e]; sic += vi[e] * vc[e];
    }
#pragma unroll
    for (int off = 16; off; off >>= 1) {
        sii += __shfl_xor_sync(0xFFFFFFFFu, sii, off);
        stt += __shfl_xor_sync(0xFFFFFFFFu, stt, off);
        scc += __shfl_xor_sync(0xFFFFFFFFu, scc, off);
        sit += __shfl_xor_sync(0xFFFFFFFFu, sit, off);
        sic += __shfl_xor_sync(0xFFFFFFFFu, sic, off);
    }
    float inva = 1.f / (sqrtf(sii) + 1e-8f);
    float invt = 1.f / (sqrtf(stt) + 1e-8f);
    float invc = 1.f / (sqrtf(scc) + 1e-8f);

    float* oa = g_an + (size_t)row * DD;
    float* ot = g_tn + (size_t)row * DD;
    float* oc = g_cn + (size_t)row * DD;
#pragma unroll
    for (int e = 0; e < 16; e++) {
        int idx = lane + 32 * e;
        oa[idx] = vi[e] * inva;
        ot[idx] = vt[e] * invt;
        oc[idx] = vc[e] * invc;
    }
    if (lane == 0) {
        float sm = sit * inva * invt;
        float smcr = sic * inva * invc;
        g_sm[row] = sm;
        g_smcr[row] = smcr;
        float mrg = margin[row];
        float mcr;
        if (*aflag) {
            float lam = fminf(fabsf(smcr) / fabsf(sm), 1.f);
            mcr = (lam + 1.f) * mrg * 0.5f;
        } else {
            mcr = mrg * 0.5f;
        }
        g_mcr[row] = mcr;
#pragma unroll
        for (int p = 0; p < 4; p++) g_best[p][row] = ~0ull;
    }
    if (blockIdx.x == 0 && threadIdx.x < 4) g_cnt[threadIdx.x] = 0;
}

// -------- kernel 2: phase-1 strip GEMM + first-valid mining over j<W1 -------
__global__ __launch_bounds__(256) void phase1_kernel(
    const float* __restrict__ margin, const int* __restrict__ labels) {
    __shared__ __align__(16) float As[BK][BM];
    __shared__ __align__(16) float Bs[BK][BN];
    __shared__ unsigned long long sbest[BM];

    int pass = blockIdx.z;
    const float *A, *Bm, *dg, *mg;
    pass_ptrs(pass, margin, A, Bm, dg, mg);

    int rowStart = blockIdx.x * BM;
    int colStart = blockIdx.y * BN;
    int tid = threadIdx.x;
    int tx = tid & 15, ty = tid >> 4;

    if (tid < BM) sbest[tid] = ~0ull;

    float acc[4][4];
#pragma unroll
    for (int i = 0; i < 4; i++)
#pragma unroll
        for (int j = 0; j < 4; j++) acc[i][j] = 0.f;

    for (int k0 = 0; k0 < DD; k0 += BK) {
#pragma unroll
        for (int q = tid; q < (BM * BK) / 4; q += 256) {
            int r = q >> 3;
            int kk = (q & 7) << 2;
            float4 va = *(const float4*)&A[(size_t)(rowStart + r) * DD + k0 + kk];
            As[kk + 0][r] = va.x; As[kk + 1][r] = va.y;
            As[kk + 2][r] = va.z; As[kk + 3][r] = va.w;
            float4 vb = *(const float4*)&Bm[(size_t)(colStart + r) * DD + k0 + kk];
            Bs[kk + 0][r] = vb.x; Bs[kk + 1][r] = vb.y;
            Bs[kk + 2][r] = vb.z; Bs[kk + 3][r] = vb.w;
        }
        __syncthreads();
#pragma unroll
        for (int k = 0; k < BK; k++) {
            float4 a = *(const float4*)&As[k][ty << 2];
            float4 b = *(const float4*)&Bs[k][tx << 2];
            float av[4] = {a.x, a.y, a.z, a.w};
            float bv[4] = {b.x, b.y, b.z, b.w};
#pragma unroll
            for (int i = 0; i < 4; i++)
#pragma unroll
                for (int j = 0; j < 4; j++) acc[i][j] += av[i] * bv[j];
        }
        __syncthreads();
    }

    // mining epilogue
    int labc[4];
#pragma unroll
    for (int j = 0; j < 4; j++) labc[j] = labels[colStart + (tx << 2) + j];

#pragma unroll
    for (int i = 0; i < 4; i++) {
        int a = rowStart + (ty << 2) + i;
        float d = dg[a];
        float m = mg[a];
        int la = labels[a];
        unsigned long long best = ~0ull;
#pragma unroll
        for (int j = 0; j < 4; j++) {
            float loss = acc[i][j] - d + m;
            if (loss > 0.f && loss < m && labc[j] != la) {
                int c = colStart + (tx << 2) + j;
                unsigned long long key =
                    ((unsigned long long)c << 32) | (unsigned long long)__float_as_uint(loss);
                best = umin64(best, key);
            }
        }
        if (best != ~0ull) atomicMin(&sbest[(ty << 2) + i], best);
    }
    __syncthreads();
    if (tid < BM && sbest[tid] != ~0ull)
        atomicMin(&g_best[pass][rowStart + tid], sbest[tid]);
}

// -------- kernel 3: gather unresolved anchors --------
__global__ __launch_bounds__(256) void collect_kernel(
    const float* __restrict__ margin, const int* __restrict__ aflag) {
    int a = blockIdx.x * 256 + threadIdx.x;
    int pass = blockIdx.y;
    int af = *aflag;
    bool okm;
    if (pass < 2) okm = af ? (margin[a] >= 0.16f) : true;
    else          okm = af ? (g_mcr[a] >= 0.16f) : true;
    if (okm && g_best[pass][a] == ~0ull) {
        int p = atomicAdd(&g_cnt[pass], 1);
        g_list[pass][p] = a;
    }
}

// -------- kernel 4: phase-2, remaining candidates for unresolved anchors ----
__global__ __launch_bounds__(256) void phase2_kernel(
    const float* __restrict__ margin, const int* __restrict__ labels) {
    const int CHUNK = 512, NCHUNK = 16;
    int pass = blockIdx.y;
    const float *A, *Bm, *dg, *mg;
    pass_ptrs(pass, margin, A, Bm, dg, mg);
    int cnt = g_cnt[pass];
    int total = cnt * NCHUNK;

    __shared__ float sAnch[DD];
    __shared__ unsigned long long sb;

    for (int w = blockIdx.x; w < total; w += gridDim.x) {
        int slot = w >> 4;
        int ch = w & 15;
        int a = g_list[pass][slot];
        int cbeg = W1 + ch * CHUNK;
        int cend = min(BB, cbeg + CHUNK);
        __syncthreads();  // protect smem reuse across work items
        for (int i = threadIdx.x; i < DD; i += 256) sAnch[i] = A[(size_t)a * DD + i];
        if (threadIdx.x == 0) sb = ~0ull;
        __syncthreads();

        float d = dg[a], m = mg[a];
        int la = labels[a];
        int wid = threadIdx.x >> 5, lane = threadIdx.x & 31;
        unsigned long long best = ~0ull;
        for (int c = cbeg + wid; c < cend; c += 8) {
            const float* brow = Bm + (size_t)c * DD;
            float s = 0.f;
#pragma unroll
            for (int e = 0; e < 16; e++) s += brow[lane + 32 * e] * sAnch[lane + 32 * e];
#pragma unroll
            for (int off = 16; off; off >>= 1) s += __shfl_xor_sync(0xFFFFFFFFu, s, off);
            if (lane == 0) {
                float loss = s - d + m;
                if (loss > 0.f && loss < m && labels[c] != la) {
                    unsigned long long key =
                        ((unsigned long long)c << 32) | (unsigned long long)__float_as_uint(loss);
                    best = umin64(best, key);
                }
            }
        }
        if (lane == 0 && best != ~0ull) atomicMin(&sb, best);
        __syncthreads();
        if (threadIdx.x == 0 && sb != ~0ull) atomicMin(&g_best[pass][a], sb);
    }
}

// -------- kernel 5: final reduction --------
__global__ __launch_bounds__(256) void final_kernel(
    const float* __restrict__ margin, const int* __restrict__ aflag,
    const float* __restrict__ crbeta, float* __restrict__ out) {
    __shared__ double sh1[256], sh2[256];
    int tid = threadIdx.x;
    int af = *aflag;
    double s1 = 0.0, s2 = 0.0;
    for (int a = tid; a < BB; a += 256) {
        bool okb = af ? (margin[a] >= 0.16f) : true;
        bool okc = af ? (g_mcr[a] >= 0.16f) : true;
        unsigned long long v;
        v = g_best[0][a];
        if (okb && v != ~0ull) s1 += (double)__uint_as_float((unsigned)v);
        v = g_best[1][a];
        if (okb && v != ~0ull) s1 += (double)__uint_as_float((unsigned)v);
        v = g_best[2][a];
        if (okc && v != ~0ull) s2 += (double)__uint_as_float((unsigned)v);
        v = g_best[3][a];
        if (okc && v != ~0ull) s2 += (double)__uint_as_float((unsigned)v);
    }
    sh1[tid] = s1; sh2[tid] = s2;
    __syncthreads();
    for (int s = 128; s; s >>= 1) {
        if (tid < s) { sh1[tid] += sh1[tid + s]; sh2[tid] += sh2[tid + s]; }
        __syncthreads();
    }
    if (tid == 0) out[0] = (float)(sh1[0] + (double)crbeta[0] * sh2[0]);
}

extern "C" void kernel_launch(void* const* d_in, const int* in_sizes, int n_in,
                              void* d_out, int out_size) {
    const float* img    = (const float*)d_in[0];
    const float* txt    = (const float*)d_in[1];
    const float* txtcr  = (const float*)d_in[2];
    const int*   labels = (const int*)d_in[3];
    const int*   aflag  = (const int*)d_in[4];
    const float* margin = (const float*)d_in[5];
    const float* crbeta = (const float*)d_in[6];
    float* out = (float*)d_out;

    prep_kernel<<<BB / 8, 256>>>(img, txt, txtcr, margin, aflag);
    phase1_kernel<<<dim3(BB / BM, W1 / BN, 4), 256>>>(margin, labels);
    collect_kernel<<<dim3(BB / 256, 4), 256>>>(margin, aflag);
    phase2_kernel<<<dim3(256, 4), 256>>>(margin, labels);
    final_kernel<<<1, 256>>>(margin, aflag, crbeta, out);
}

// round 2
// speedup vs baseline: 1.4944x; 1.4944x over previous
#include <cuda_runtime.h>
#include <cuda_bf16.h>

#define BB 8192
#define DD 512
#define W1 128          // phase-1 candidate window
#define BM 128
#define BN 128
#define BK 16
#define P1 132          // padded smem row (floats): 16B-aligned rows, 2-way STS worst case

// -------- scratch (device globals; no allocation allowed) --------
__device__ float g_an[BB * DD];   // normalized img
__device__ float g_tn[BB * DD];   // normalized txt
__device__ float g_cn[BB * DD];   // normalized txt_cr
__device__ float g_sm[BB];        // diag(sim)
__device__ float g_smcr[BB];      // diag(sim_cr)
__device__ float g_mcr[BB];       // margin_cr per row
__device__ unsigned long long g_best[4][BB];  // (j<<32)|float_bits(loss), ~0 = none
__device__ int g_cnt[4];
__device__ int g_list[4][BB];

static __device__ __forceinline__ unsigned long long umin64(unsigned long long a,
                                                            unsigned long long b) {
    return a < b ? a : b;
}

// pass 0: sim rows / 1: sim cols / 2: sim_cr rows / 3: sim_cr cols
static __device__ __forceinline__ void pass_ptrs(int pass, const float* margin,
                                                 const float*& A, const float*& Bm,
                                                 const float*& dg, const float*& mg) {
    switch (pass) {
        case 0: A = g_an; Bm = g_tn; dg = g_sm;   mg = margin; break;
        case 1: A = g_tn; Bm = g_an; dg = g_sm;   mg = margin; break;
        case 2: A = g_an; Bm = g_cn; dg = g_smcr; mg = g_mcr;  break;
        default:A = g_cn; Bm = g_an; dg = g_smcr; mg = g_mcr;  break;
    }
}

// -------- kernel 1: row-normalize, diag sims, margin_cr, state reset --------
__global__ __launch_bounds__(256) void prep_kernel(
    const float* __restrict__ img, const float* __restrict__ txt,
    const float* __restrict__ cr, const float* __restrict__ margin,
    const int* __restrict__ aflag) {
    int row = blockIdx.x * 8 + (threadIdx.x >> 5);
    int lane = threadIdx.x & 31;
    const float* pi = img + (size_t)row * DD;
    const float* pt = txt + (size_t)row * DD;
    const float* pc = cr + (size_t)row * DD;

    float vi[16], vt[16], vc[16];
    float sii = 0.f, stt = 0.f, scc = 0.f, sit = 0.f, sic = 0.f;
#pragma unroll
    for (int e = 0; e < 16; e++) {
        int idx = lane + 32 * e;
        vi[e] = pi[idx]; vt[e] = pt[idx]; vc[e] = pc[idx];
        sii += vi[e] * vi[e]; stt += vt[e] * vt[e]; scc += vc[e] * vc[e];
        sit += vi[e] * vt[e]; sic += vi[e] * vc[e];
    }
#pragma unroll
    for (int off = 16; off; off >>= 1) {
        sii += __shfl_xor_sync(0xFFFFFFFFu, sii, off);
        stt += __shfl_xor_sync(0xFFFFFFFFu, stt, off);
        scc += __shfl_xor_sync(0xFFFFFFFFu, scc, off);
        sit += __shfl_xor_sync(0xFFFFFFFFu, sit, off);
        sic += __shfl_xor_sync(0xFFFFFFFFu, sic, off);
    }
    float inva = 1.f / (sqrtf(sii) + 1e-8f);
    float invt = 1.f / (sqrtf(stt) + 1e-8f);
    float invc = 1.f / (sqrtf(scc) + 1e-8f);

    float* oa = g_an + (size_t)row * DD;
    float* ot = g_tn + (size_t)row * DD;
    float* oc = g_cn + (size_t)row * DD;
#pragma unroll
    for (int e = 0; e < 16; e++) {
        int idx = lane + 32 * e;
        oa[idx] = vi[e] * inva;
        ot[idx] = vt[e] * invt;
        oc[idx] = vc[e] * invc;
    }
    if (lane == 0) {
        float sm = sit * inva * invt;
        float smcr = sic * inva * invc;
        g_sm[row] = sm;
        g_smcr[row] = smcr;
        float mrg = margin[row];
        float mcr;
        if (*aflag) {
            float lam = fminf(fabsf(smcr) / fabsf(sm), 1.f);
            mcr = (lam + 1.f) * mrg * 0.5f;
        } else {
            mcr = mrg * 0.5f;
        }
        g_mcr[row] = mcr;
#pragma unroll
        for (int p = 0; p < 4; p++) g_best[p][row] = ~0ull;
    }
    if (blockIdx.x == 0 && threadIdx.x < 4) g_cnt[threadIdx.x] = 0;
}

// -------- kernel 2: phase-1 128x128 strip GEMM (packed f32x2 FMA) + mining --
__global__ __launch_bounds__(256, 2) void phase1_kernel(
    const float* __restrict__ margin, const int* __restrict__ labels) {
    __shared__ __align__(16) float As[BK * P1];
    __shared__ __align__(16) float Bs[BK * P1];
    __shared__ unsigned long long sbest[BM];

    int pass = blockIdx.y;
    const float *A, *Bm, *dg, *mg;
    pass_ptrs(pass, margin, A, Bm, dg, mg);

    int rowStart = blockIdx.x * BM;
    int tid = threadIdx.x;
    int tx = tid & 15, ty = tid >> 4;

    if (tid < BM) sbest[tid] = ~0ull;

    unsigned long long acc[8][4];
#pragma unroll
    for (int i = 0; i < 8; i++)
#pragma unroll
        for (int j = 0; j < 4; j++) acc[i][j] = 0ull;

    // global load mapping: thread covers float4 (r0, kk) and (r0+64, kk)
    int r0 = tid >> 2;
    int kk = (tid & 3) << 2;

    float4 pa0, pa1, pb0, pb1;
    pa0 = *(const float4*)&A[(size_t)(rowStart + r0) * DD + kk];
    pa1 = *(const float4*)&A[(size_t)(rowStart + r0 + 64) * DD + kk];
    pb0 = *(const float4*)&Bm[(size_t)r0 * DD + kk];
    pb1 = *(const float4*)&Bm[(size_t)(r0 + 64) * DD + kk];

    for (int k0 = 0; k0 < DD; k0 += BK) {
        __syncthreads();
        As[(kk + 0) * P1 + r0] = pa0.x; As[(kk + 1) * P1 + r0] = pa0.y;
        As[(kk + 2) * P1 + r0] = pa0.z; As[(kk + 3) * P1 + r0] = pa0.w;
        As[(kk + 0) * P1 + r0 + 64] = pa1.x; As[(kk + 1) * P1 + r0 + 64] = pa1.y;
        As[(kk + 2) * P1 + r0 + 64] = pa1.z; As[(kk + 3) * P1 + r0 + 64] = pa1.w;
        Bs[(kk + 0) * P1 + r0] = pb0.x; Bs[(kk + 1) * P1 + r0] = pb0.y;
        Bs[(kk + 2) * P1 + r0] = pb0.z; Bs[(kk + 3) * P1 + r0] = pb0.w;
        Bs[(kk + 0) * P1 + r0 + 64] = pb1.x; Bs[(kk + 1) * P1 + r0 + 64] = pb1.y;
        Bs[(kk + 2) * P1 + r0 + 64] = pb1.z; Bs[(kk + 3) * P1 + r0 + 64] = pb1.w;
        __syncthreads();

        if (k0 + BK < DD) {
            int kn = k0 + BK + kk;
            pa0 = *(const float4*)&A[(size_t)(rowStart + r0) * DD + kn];
            pa1 = *(const float4*)&A[(size_t)(rowStart + r0 + 64) * DD + kn];
            pb0 = *(const float4*)&Bm[(size_t)r0 * DD + kn];
            pb1 = *(const float4*)&Bm[(size_t)(r0 + 64) * DD + kn];
        }

#pragma unroll
        for (int k = 0; k < BK; k++) {
            float4 a0 = *(const float4*)&As[k * P1 + (ty << 2)];
            float4 a1 = *(const float4*)&As[k * P1 + 64 + (ty << 2)];
            ulonglong2 b0 = *(const ulonglong2*)&Bs[k * P1 + (tx << 2)];
            ulonglong2 b1 = *(const ulonglong2*)&Bs[k * P1 + 64 + (tx << 2)];
            float af[8] = {a0.x, a0.y, a0.z, a0.w, a1.x, a1.y, a1.z, a1.w};
#pragma unroll
            for (int i = 0; i < 8; i++) {
                unsigned long long aa;
                asm("mov.b64 %0, {%1, %1};" : "=l"(aa) : "f"(af[i]));
                asm("fma.rn.f32x2 %0, %1, %2, %0;" : "+l"(acc[i][0]) : "l"(aa), "l"(b0.x));
                asm("fma.rn.f32x2 %0, %1, %2, %0;" : "+l"(acc[i][1]) : "l"(aa), "l"(b0.y));
                asm("fma.rn.f32x2 %0, %1, %2, %0;" : "+l"(acc[i][2]) : "l"(aa), "l"(b1.x));
                asm("fma.rn.f32x2 %0, %1, %2, %0;" : "+l"(acc[i][3]) : "l"(aa), "l"(b1.y));
            }
        }
    }

    // mining epilogue: 8 rows x 8 cols per thread
    int lc[8];
#pragma unroll
    for (int jp = 0; jp < 4; jp++) {
        int cb = ((jp >> 1) ? 64 : 0) + (tx << 2) + ((jp & 1) << 1);
        lc[jp * 2 + 0] = labels[cb + 0];
        lc[jp * 2 + 1] = labels[cb + 1];
    }

#pragma unroll
    for (int i = 0; i < 8; i++) {
        int lrow = (i < 4) ? ((ty << 2) + i) : (64 + (ty << 2) + (i - 4));
        int arow = rowStart + lrow;
        float d = dg[arow];
        float m = mg[arow];
        int la = labels[arow];
        unsigned long long best = ~0ull;
#pragma unroll
        for (int jp = 0; jp < 4; jp++) {
            float lo, hi;
            asm("mov.b64 {%0, %1}, %2;" : "=f"(lo), "=f"(hi) : "l"(acc[i][jp]));
            int cb = ((jp >> 1) ? 64 : 0) + (tx << 2) + ((jp & 1) << 1);
            float loss0 = lo - d + m;
            float loss1 = hi - d + m;
            if (loss0 > 0.f && loss0 < m && lc[jp * 2 + 0] != la) {
                unsigned long long key = ((unsigned long long)cb << 32) |
                                         (unsigned long long)__float_as_uint(loss0);
                best = umin64(best, key);
            }
            if (loss1 > 0.f && loss1 < m && lc[jp * 2 + 1] != la) {
                unsigned long long key = ((unsigned long long)(cb + 1) << 32) |
                                         (unsigned long long)__float_as_uint(loss1);
                best = umin64(best, key);
            }
        }
        if (best != ~0ull) atomicMin(&sbest[lrow], best);
    }
    __syncthreads();
    if (tid < BM && sbest[tid] != ~0ull)
        atomicMin(&g_best[pass][rowStart + tid], sbest[tid]);
}

// -------- kernel 3: gather unresolved anchors --------
__global__ __launch_bounds__(256) void collect_kernel(
    const float* __restrict__ margin, const int* __restrict__ aflag) {
    int a = blockIdx.x * 256 + threadIdx.x;
    int pass = blockIdx.y;
    int af = *aflag;
    bool okm;
    if (pass < 2) okm = af ? (margin[a] >= 0.16f) : true;
    else          okm = af ? (g_mcr[a] >= 0.16f) : true;
    if (okm && g_best[pass][a] == ~0ull) {
        int p = atomicAdd(&g_cnt[pass], 1);
        g_list[pass][p] = a;
    }
}

// -------- kernel 4: phase-2, anchor in registers, float4 loads, unroll 4 ----
__global__ __launch_bounds__(256) void phase2_kernel(
    const float* __restrict__ margin, const int* __restrict__ labels) {
    const int CHUNK = 512, NCH = 16;
    int pass = blockIdx.y;
    const float *A, *Bm, *dg, *mg;
    pass_ptrs(pass, margin, A, Bm, dg, mg);
    int cnt = g_cnt[pass];
    int total = cnt * NCH;
    int wid = threadIdx.x >> 5, lane = threadIdx.x & 31;

    for (int w = blockIdx.x; w < total; w += gridDim.x) {
        int slot = w >> 4;
        int ch = w & 15;
        int a = g_list[pass][slot];
        int cbeg = W1 + ch * CHUNK;
        int cend = min(BB, cbeg + CHUNK);

        // anchor into registers: element map 4*(lane + 32*e)
        const float4* ap = (const float4*)(A + (size_t)a * DD);
        float4 av[4];
#pragma unroll
        for (int e = 0; e < 4; e++) av[e] = ap[lane + 32 * e];

        float d = dg[a], m = mg[a];
        int la = labels[a];
        unsigned long long best = ~0ull;

        int start = cbeg + wid * 64;
        int end = min(cend, start + 64);
        for (int c0 = start; c0 < end; c0 += 4) {
            float s0 = 0.f, s1 = 0.f, s2 = 0.f, s3 = 0.f;
            const float4* cp0 = (const float4*)(Bm + (size_t)(c0 + 0) * DD);
            const float4* cp1 = (const float4*)(Bm + (size_t)(c0 + 1) * DD);
            const float4* cp2 = (const float4*)(Bm + (size_t)(c0 + 2) * DD);
            const float4* cp3 = (const float4*)(Bm + (size_t)(c0 + 3) * DD);
#pragma unroll
            for (int e = 0; e < 4; e++) {
                float4 v0 = cp0[lane + 32 * e];
                float4 v1 = cp1[lane + 32 * e];
                float4 v2 = cp2[lane + 32 * e];
                float4 v3 = cp3[lane + 32 * e];
                s0 += av[e].x * v0.x + av[e].y * v0.y + av[e].z * v0.z + av[e].w * v0.w;
                s1 += av[e].x * v1.x + av[e].y * v1.y + av[e].z * v1.z + av[e].w * v1.w;
                s2 += av[e].x * v2.x + av[e].y * v2.y + av[e].z * v2.z + av[e].w * v2.w;
                s3 += av[e].x * v3.x + av[e].y * v3.y + av[e].z * v3.z + av[e].w * v3.w;
            }
#pragma unroll
            for (int off = 16; off; off >>= 1) {
                s0 += __shfl_xor_sync(0xFFFFFFFFu, s0, off);
                s1 += __shfl_xor_sync(0xFFFFFFFFu, s1, off);
                s2 += __shfl_xor_sync(0xFFFFFFFFu, s2, off);
                s3 += __shfl_xor_sync(0xFFFFFFFFu, s3, off);
            }
            if (lane == 0) {
                float sv[4] = {s0, s1, s2, s3};
#pragma unroll
                for (int u = 0; u < 4; u++) {
                    float loss = sv[u] - d + m;
                    if (loss > 0.f && loss < m && labels[c0 + u] != la) {
                        unsigned long long key =
                            ((unsigned long long)(c0 + u) << 32) |
                            (unsigned long long)__float_as_uint(loss);
                        best = umin64(best, key);
                    }
                }
            }
        }
        if (lane == 0 && best != ~0ull) atomicMin(&g_best[pass][a], best);
    }
}

// -------- kernel 5: final reduction --------
__global__ __launch_bounds__(256) void final_kernel(
    const float* __restrict__ margin, const int* __restrict__ aflag,
    const float* __restrict__ crbeta, float* __restrict__ out) {
    __shared__ double sh1[256], sh2[256];
    int tid = threadIdx.x;
    int af = *aflag;
    double s1 = 0.0, s2 = 0.0;
    for (int a = tid; a < BB; a += 256) {
        bool okb = af ? (margin[a] >= 0.16f) : true;
        bool okc = af ? (g_mcr[a] >= 0.16f) : true;
        unsigned long long v;
        v = g_best[0][a];
        if (okb && v != ~0ull) s1 += (double)__uint_as_float((unsigned)v);
        v = g_best[1][a];
        if (okb && v != ~0ull) s1 += (double)__uint_as_float((unsigned)v);
        v = g_best[2][a];
        if (okc && v != ~0ull) s2 += (double)__uint_as_float((unsigned)v);
        v = g_best[3][a];
        if (okc && v != ~0ull) s2 += (double)__uint_as_float((unsigned)v);
    }
    sh1[tid] = s1; sh2[tid] = s2;
    __syncthreads();
    for (int s = 128; s; s >>= 1) {
        if (tid < s) { sh1[tid] += sh1[tid + s]; sh2[tid] += sh2[tid + s]; }
        __syncthreads();
    }
    if (tid == 0) out[0] = (float)(sh1[0] + (double)crbeta[0] * sh2[0]);
}

extern "C" void kernel_launch(void* const* d_in, const int* in_sizes, int n_in,
                              void* d_out, int out_size) {
    const float* img    = (const float*)d_in[0];
    const float* txt    = (const float*)d_in[1];
    const float* txtcr  = (const float*)d_in[2];
    const int*   labels = (const int*)d_in[3];
    const int*   aflag  = (const int*)d_in[4];
    const float* margin = (const float*)d_in[5];
    const float* crbeta = (const float*)d_in[6];
    float* out = (float*)d_out;

    prep_kernel<<<BB / 8, 256>>>(img, txt, txtcr, margin, aflag);
    phase1_kernel<<<dim3(BB / BM, 4), 256>>>(margin, labels);
    collect_kernel<<<dim3(BB / 256, 4), 256>>>(margin, aflag);
    phase2_kernel<<<dim3(1024, 4), 256>>>(margin, labels);
    final_kernel<<<1, 256>>>(margin, aflag, crbeta, out);
}

// round 3
// speedup vs baseline: 2.0509x; 1.3724x over previous
#include <cuda_runtime.h>
#include <cuda_bf16.h>

#define BB 8192
#define DD 512
#define W1 128          // phase-1 candidate window
#define BM 128
#define BN 128
#define BK 16
#define P1 132          // padded smem row (floats)
#define P2A 68          // phase2 A smem pad (64 rows + 4)

// -------- scratch (device globals; no allocation allowed) --------
__device__ float g_an[BB * DD];   // normalized img
__device__ float g_tn[BB * DD];   // normalized txt
__device__ float g_cn[BB * DD];   // normalized txt_cr
__device__ float g_sm[BB];        // diag(sim)
__device__ float g_smcr[BB];      // diag(sim_cr)
__device__ float g_mcr[BB];       // margin_cr per row
__device__ unsigned long long g_best[4][BB];  // (j<<32)|float_bits(loss), ~0 = none
__device__ int g_cnt[4];
__device__ int g_list[4][BB];

static __device__ __forceinline__ unsigned long long umin64(unsigned long long a,
                                                            unsigned long long b) {
    return a < b ? a : b;
}

// pass 0: sim rows / 1: sim cols / 2: sim_cr rows / 3: sim_cr cols
static __device__ __forceinline__ void pass_ptrs(int pass, const float* margin,
                                                 const float*& A, const float*& Bm,
                                                 const float*& dg, const float*& mg) {
    switch (pass) {
        case 0: A = g_an; Bm = g_tn; dg = g_sm;   mg = margin; break;
        case 1: A = g_tn; Bm = g_an; dg = g_sm;   mg = margin; break;
        case 2: A = g_an; Bm = g_cn; dg = g_smcr; mg = g_mcr;  break;
        default:A = g_cn; Bm = g_an; dg = g_smcr; mg = g_mcr;  break;
    }
}

// -------- kernel 1: row-normalize, diag sims, margin_cr, state reset --------
__global__ __launch_bounds__(256) void prep_kernel(
    const float* __restrict__ img, const float* __restrict__ txt,
    const float* __restrict__ cr, const float* __restrict__ margin,
    const int* __restrict__ aflag) {
    int row = blockIdx.x * 8 + (threadIdx.x >> 5);
    int lane = threadIdx.x & 31;
    const float* pi = img + (size_t)row * DD;
    const float* pt = txt + (size_t)row * DD;
    const float* pc = cr + (size_t)row * DD;

    float vi[16], vt[16], vc[16];
    float sii = 0.f, stt = 0.f, scc = 0.f, sit = 0.f, sic = 0.f;
#pragma unroll
    for (int e = 0; e < 16; e++) {
        int idx = lane + 32 * e;
        vi[e] = pi[idx]; vt[e] = pt[idx]; vc[e] = pc[idx];
        sii += vi[e] * vi[e]; stt += vt[e] * vt[e]; scc += vc[e] * vc[e];
        sit += vi[e] * vt[e]; sic += vi[e] * vc[e];
    }
#pragma unroll
    for (int off = 16; off; off >>= 1) {
        sii += __shfl_xor_sync(0xFFFFFFFFu, sii, off);
        stt += __shfl_xor_sync(0xFFFFFFFFu, stt, off);
        scc += __shfl_xor_sync(0xFFFFFFFFu, scc, off);
        sit += __shfl_xor_sync(0xFFFFFFFFu, sit, off);
        sic += __shfl_xor_sync(0xFFFFFFFFu, sic, off);
    }
    float inva = 1.f / (sqrtf(sii) + 1e-8f);
    float invt = 1.f / (sqrtf(stt) + 1e-8f);
    float invc = 1.f / (sqrtf(scc) + 1e-8f);

    float* oa = g_an + (size_t)row * DD;
    float* ot = g_tn + (size_t)row * DD;
    float* oc = g_cn + (size_t)row * DD;
#pragma unroll
    for (int e = 0; e < 16; e++) {
        int idx = lane + 32 * e;
        oa[idx] = vi[e] * inva;
        ot[idx] = vt[e] * invt;
        oc[idx] = vc[e] * invc;
    }
    if (lane == 0) {
        float sm = sit * inva * invt;
        float smcr = sic * inva * invc;
        g_sm[row] = sm;
        g_smcr[row] = smcr;
        float mrg = margin[row];
        float mcr;
        if (*aflag) {
            float lam = fminf(fabsf(smcr) / fabsf(sm), 1.f);
            mcr = (lam + 1.f) * mrg * 0.5f;
        } else {
            mcr = mrg * 0.5f;
        }
        g_mcr[row] = mcr;
#pragma unroll
        for (int p = 0; p < 4; p++) g_best[p][row] = ~0ull;
    }
    if (blockIdx.x == 0 && threadIdx.x < 4) g_cnt[threadIdx.x] = 0;
}

// -------- kernel 2: phase-1 128x128 strip GEMM (packed f32x2 FMA) + mining --
__global__ __launch_bounds__(256, 2) void phase1_kernel(
    const float* __restrict__ margin, const int* __restrict__ labels) {
    __shared__ __align__(16) float As[BK * P1];
    __shared__ __align__(16) float Bs[BK * P1];
    __shared__ unsigned long long sbest[BM];

    int pass = blockIdx.y;
    const float *A, *Bm, *dg, *mg;
    pass_ptrs(pass, margin, A, Bm, dg, mg);

    int rowStart = blockIdx.x * BM;
    int tid = threadIdx.x;
    int tx = tid & 15, ty = tid >> 4;

    if (tid < BM) sbest[tid] = ~0ull;

    unsigned long long acc[8][4];
#pragma unroll
    for (int i = 0; i < 8; i++)
#pragma unroll
        for (int j = 0; j < 4; j++) acc[i][j] = 0ull;

    int r0 = tid >> 2;
    int kk = (tid & 3) << 2;

    float4 pa0, pa1, pb0, pb1;
    pa0 = *(const float4*)&A[(size_t)(rowStart + r0) * DD + kk];
    pa1 = *(const float4*)&A[(size_t)(rowStart + r0 + 64) * DD + kk];
    pb0 = *(const float4*)&Bm[(size_t)r0 * DD + kk];
    pb1 = *(const float4*)&Bm[(size_t)(r0 + 64) * DD + kk];

    for (int k0 = 0; k0 < DD; k0 += BK) {
        __syncthreads();
        As[(kk + 0) * P1 + r0] = pa0.x; As[(kk + 1) * P1 + r0] = pa0.y;
        As[(kk + 2) * P1 + r0] = pa0.z; As[(kk + 3) * P1 + r0] = pa0.w;
        As[(kk + 0) * P1 + r0 + 64] = pa1.x; As[(kk + 1) * P1 + r0 + 64] = pa1.y;
        As[(kk + 2) * P1 + r0 + 64] = pa1.z; As[(kk + 3) * P1 + r0 + 64] = pa1.w;
        Bs[(kk + 0) * P1 + r0] = pb0.x; Bs[(kk + 1) * P1 + r0] = pb0.y;
        Bs[(kk + 2) * P1 + r0] = pb0.z; Bs[(kk + 3) * P1 + r0] = pb0.w;
        Bs[(kk + 0) * P1 + r0 + 64] = pb1.x; Bs[(kk + 1) * P1 + r0 + 64] = pb1.y;
        Bs[(kk + 2) * P1 + r0 + 64] = pb1.z; Bs[(kk + 3) * P1 + r0 + 64] = pb1.w;
        __syncthreads();

        if (k0 + BK < DD) {
            int kn = k0 + BK + kk;
            pa0 = *(const float4*)&A[(size_t)(rowStart + r0) * DD + kn];
            pa1 = *(const float4*)&A[(size_t)(rowStart + r0 + 64) * DD + kn];
            pb0 = *(const float4*)&Bm[(size_t)r0 * DD + kn];
            pb1 = *(const float4*)&Bm[(size_t)(r0 + 64) * DD + kn];
        }

#pragma unroll
        for (int k = 0; k < BK; k++) {
            float4 a0 = *(const float4*)&As[k * P1 + (ty << 2)];
            float4 a1 = *(const float4*)&As[k * P1 + 64 + (ty << 2)];
            ulonglong2 b0 = *(const ulonglong2*)&Bs[k * P1 + (tx << 2)];
            ulonglong2 b1 = *(const ulonglong2*)&Bs[k * P1 + 64 + (tx << 2)];
            float af[8] = {a0.x, a0.y, a0.z, a0.w, a1.x, a1.y, a1.z, a1.w};
#pragma unroll
            for (int i = 0; i < 8; i++) {
                unsigned long long aa;
                asm("mov.b64 %0, {%1, %1};" : "=l"(aa) : "f"(af[i]));
                asm("fma.rn.f32x2 %0, %1, %2, %0;" : "+l"(acc[i][0]) : "l"(aa), "l"(b0.x));
                asm("fma.rn.f32x2 %0, %1, %2, %0;" : "+l"(acc[i][1]) : "l"(aa), "l"(b0.y));
                asm("fma.rn.f32x2 %0, %1, %2, %0;" : "+l"(acc[i][2]) : "l"(aa), "l"(b1.x));
                asm("fma.rn.f32x2 %0, %1, %2, %0;" : "+l"(acc[i][3]) : "l"(aa), "l"(b1.y));
            }
        }
    }

    int lc[8];
#pragma unroll
    for (int jp = 0; jp < 4; jp++) {
        int cb = ((jp >> 1) ? 64 : 0) + (tx << 2) + ((jp & 1) << 1);
        lc[jp * 2 + 0] = labels[cb + 0];
        lc[jp * 2 + 1] = labels[cb + 1];
    }

#pragma unroll
    for (int i = 0; i < 8; i++) {
        int lrow = (i < 4) ? ((ty << 2) + i) : (64 + (ty << 2) + (i - 4));
        int arow = rowStart + lrow;
        float d = dg[arow];
        float m = mg[arow];
        int la = labels[arow];
        unsigned long long best = ~0ull;
#pragma unroll
        for (int jp = 0; jp < 4; jp++) {
            float lo, hi;
            asm("mov.b64 {%0, %1}, %2;" : "=f"(lo), "=f"(hi) : "l"(acc[i][jp]));
            int cb = ((jp >> 1) ? 64 : 0) + (tx << 2) + ((jp & 1) << 1);
            float loss0 = lo - d + m;
            float loss1 = hi - d + m;
            if (loss0 > 0.f && loss0 < m && lc[jp * 2 + 0] != la) {
                unsigned long long key = ((unsigned long long)cb << 32) |
                                         (unsigned long long)__float_as_uint(loss0);
                best = umin64(best, key);
            }
            if (loss1 > 0.f && loss1 < m && lc[jp * 2 + 1] != la) {
                unsigned long long key = ((unsigned long long)(cb + 1) << 32) |
                                         (unsigned long long)__float_as_uint(loss1);
                best = umin64(best, key);
            }
        }
        if (best != ~0ull) atomicMin(&sbest[lrow], best);
    }
    __syncthreads();
    if (tid < BM && sbest[tid] != ~0ull)
        atomicMin(&g_best[pass][rowStart + tid], sbest[tid]);
}

// -------- kernel 3: gather unresolved anchors --------
__global__ __launch_bounds__(256) void collect_kernel(
    const float* __restrict__ margin, const int* __restrict__ aflag) {
    int a = blockIdx.x * 256 + threadIdx.x;
    int pass = blockIdx.y;
    int af = *aflag;
    bool okm;
    if (pass < 2) okm = af ? (margin[a] >= 0.16f) : true;
    else          okm = af ? (g_mcr[a] >= 0.16f) : true;
    if (okm && g_best[pass][a] == ~0ull) {
        int p = atomicAdd(&g_cnt[pass], 1);
        g_list[pass][p] = a;
    }
}

// -------- kernel 4: phase-2 gathered 64x128x512 GEMM over unresolved -------
__global__ __launch_bounds__(256) void phase2_kernel(
    const float* __restrict__ margin, const int* __restrict__ labels) {
    __shared__ __align__(16) float As[BK * P2A];
    __shared__ __align__(16) float Bs[BK * P1];
    __shared__ int sList[64];
    __shared__ unsigned long long sbest[64];

    int pass = blockIdx.y;
    const float *A, *Bm, *dg, *mg;
    pass_ptrs(pass, margin, A, Bm, dg, mg);
    int cnt = g_cnt[pass];

    int colStart = W1 + blockIdx.x * BN;   // blockIdx.x in [0, 63)
    int tid = threadIdx.x;
    int tx = tid & 15, ty = tid >> 4;
    int r0 = tid >> 2;
    int kk = (tid & 3) << 2;

    for (int base = 0; base < cnt; base += 64) {
        __syncthreads();   // protect smem reuse across row-blocks
        if (tid < 64) {
            int idx = base + tid;
            sList[tid] = (idx < cnt) ? g_list[pass][idx] : g_list[pass][0];
            sbest[tid] = ~0ull;
        }
        __syncthreads();

        unsigned long long acc[4][4];
#pragma unroll
        for (int i = 0; i < 4; i++)
#pragma unroll
            for (int j = 0; j < 4; j++) acc[i][j] = 0ull;

        const float* aRowPtr = A + (size_t)sList[r0] * DD + kk;

        for (int k0 = 0; k0 < DD; k0 += BK) {
            float4 va = *(const float4*)(aRowPtr + k0);
            float4 vb0 = *(const float4*)&Bm[(size_t)(colStart + r0) * DD + k0 + kk];
            float4 vb1 = *(const float4*)&Bm[(size_t)(colStart + r0 + 64) * DD + k0 + kk];
            __syncthreads();
            As[(kk + 0) * P2A + r0] = va.x; As[(kk + 1) * P2A + r0] = va.y;
            As[(kk + 2) * P2A + r0] = va.z; As[(kk + 3) * P2A + r0] = va.w;
            Bs[(kk + 0) * P1 + r0] = vb0.x; Bs[(kk + 1) * P1 + r0] = vb0.y;
            Bs[(kk + 2) * P1 + r0] = vb0.z; Bs[(kk + 3) * P1 + r0] = vb0.w;
            Bs[(kk + 0) * P1 + r0 + 64] = vb1.x; Bs[(kk + 1) * P1 + r0 + 64] = vb1.y;
            Bs[(kk + 2) * P1 + r0 + 64] = vb1.z; Bs[(kk + 3) * P1 + r0 + 64] = vb1.w;
            __syncthreads();

#pragma unroll
            for (int k = 0; k < BK; k++) {
                float4 a0 = *(const float4*)&As[k * P2A + (ty << 2)];
                ulonglong2 b0 = *(const ulonglong2*)&Bs[k * P1 + (tx << 2)];
                ulonglong2 b1 = *(const ulonglong2*)&Bs[k * P1 + 64 + (tx << 2)];
                float af[4] = {a0.x, a0.y, a0.z, a0.w};
#pragma unroll
                for (int i = 0; i < 4; i++) {
                    unsigned long long aa;
                    asm("mov.b64 %0, {%1, %1};" : "=l"(aa) : "f"(af[i]));
                    asm("fma.rn.f32x2 %0, %1, %2, %0;" : "+l"(acc[i][0]) : "l"(aa), "l"(b0.x));
                    asm("fma.rn.f32x2 %0, %1, %2, %0;" : "+l"(acc[i][1]) : "l"(aa), "l"(b0.y));
                    asm("fma.rn.f32x2 %0, %1, %2, %0;" : "+l"(acc[i][2]) : "l"(aa), "l"(b1.x));
                    asm("fma.rn.f32x2 %0, %1, %2, %0;" : "+l"(acc[i][3]) : "l"(aa), "l"(b1.y));
                }
            }
        }

        // mining epilogue
#pragma unroll
        for (int i = 0; i < 4; i++) {
            int lr = (ty << 2) + i;
            if (base + lr >= cnt) continue;
            int arow = sList[lr];
            float d = dg[arow];
            float m = mg[arow];
            int la = labels[arow];
            unsigned long long best = ~0ull;
#pragma unroll
            for (int jp = 0; jp < 4; jp++) {
                float lo, hi;
                asm("mov.b64 {%0, %1}, %2;" : "=f"(lo), "=f"(hi) : "l"(acc[i][jp]));
                int cb = colStart + ((jp >> 1) ? 64 : 0) + (tx << 2) + ((jp & 1) << 1);
                float loss0 = lo - d + m;
                float loss1 = hi - d + m;
                if (loss0 > 0.f && loss0 < m && labels[cb] != la) {
                    unsigned long long key = ((unsigned long long)cb << 32) |
                                             (unsigned long long)__float_as_uint(loss0);
                    best = umin64(best, key);
                }
                if (loss1 > 0.f && loss1 < m && labels[cb + 1] != la) {
                    unsigned long long key = ((unsigned long long)(cb + 1) << 32) |
                                             (unsigned long long)__float_as_uint(loss1);
                    best = umin64(best, key);
                }
            }
            if (best != ~0ull) atomicMin(&sbest[lr], best);
        }
        __syncthreads();
        if (tid < 64 && base + tid < cnt && sbest[tid] != ~0ull)
            atomicMin(&g_best[pass][sList[tid]], sbest[tid]);
    }
}

// -------- kernel 5: final reduction --------
__global__ __launch_bounds__(256) void final_kernel(
    const float* __restrict__ margin, const int* __restrict__ aflag,
    const float* __restrict__ crbeta, float* __restrict__ out) {
    __shared__ double sh1[256], sh2[256];
    int tid = threadIdx.x;
    int af = *aflag;
    double s1 = 0.0, s2 = 0.0;
    for (int a = tid; a < BB; a += 256) {
        bool okb = af ? (margin[a] >= 0.16f) : true;
        bool okc = af ? (g_mcr[a] >= 0.16f) : true;
        unsigned long long v;
        v = g_best[0][a];
        if (okb && v != ~0ull) s1 += (double)__uint_as_float((unsigned)v);
        v = g_best[1][a];
        if (okb && v != ~0ull) s1 += (double)__uint_as_float((unsigned)v);
        v = g_best[2][a];
        if (okc && v != ~0ull) s2 += (double)__uint_as_float((unsigned)v);
        v = g_best[3][a];
        if (okc && v != ~0ull) s2 += (double)__uint_as_float((unsigned)v);
    }
    sh1[tid] = s1; sh2[tid] = s2;
    __syncthreads();
    for (int s = 128; s; s >>= 1) {
        if (tid < s) { sh1[tid] += sh1[tid + s]; sh2[tid] += sh2[tid + s]; }
        __syncthreads();
    }
    if (tid == 0) out[0] = (float)(sh1[0] + (double)crbeta[0] * sh2[0]);
}

extern "C" void kernel_launch(void* const* d_in, const int* in_sizes, int n_in,
                              void* d_out, int out_size) {
    const float* img    = (const float*)d_in[0];
    const float* txt    = (const float*)d_in[1];
    const float* txtcr  = (const float*)d_in[2];
    const int*   labels = (const int*)d_in[3];
    const int*   aflag  = (const int*)d_in[4];
    const float* margin = (const float*)d_in[5];
    const float* crbeta = (const float*)d_in[6];
    float* out = (float*)d_out;

    prep_kernel<<<BB / 8, 256>>>(img, txt, txtcr, margin, aflag);
    phase1_kernel<<<dim3(BB / BM, 4), 256>>>(margin, labels);
    collect_kernel<<<dim3(BB / 256, 4), 256>>>(margin, aflag);
    phase2_kernel<<<dim3((BB - W1) / BN, 4), 256>>>(margin, labels);
    final_kernel<<<1, 256>>>(margin, aflag, crbeta, out);
}

// round 4
// speedup vs baseline: 2.1955x; 1.0705x over previous
#include <cuda_runtime.h>
#include <cuda_bf16.h>

#define BB 8192
#define DD 512
#define W1 128          // phase-1 candidate window
#define BM 128
#define BN 128
#define BK 16
#define P1 132          // padded smem row (floats)
#define P2A 68          // phase2 A smem pad

// -------- scratch (device globals; no allocation allowed) --------
__device__ float g_inva[BB];      // 1/(|img_row|+eps)
__device__ float g_invt[BB];      // 1/(|txt_row|+eps)
__device__ float g_invc[BB];      // 1/(|cr_row|+eps)
__device__ float g_sm[BB];        // diag(sim)
__device__ float g_smcr[BB];      // diag(sim_cr)
__device__ float g_mcr[BB];       // margin_cr per row
__device__ unsigned long long g_best[4][BB];  // (j<<32)|float_bits(loss), ~0 = none
__device__ int g_cnt[4];
__device__ int g_list[4][BB];

static __device__ __forceinline__ unsigned long long umin64(unsigned long long a,
                                                            unsigned long long b) {
    return a < b ? a : b;
}

// pass 0: sim rows / 1: sim cols / 2: sim_cr rows / 3: sim_cr cols
// A/Bm are RAW inputs; iA/iB are per-row inverse norms applied at STS time.
static __device__ __forceinline__ void pass_ptrs(
    int pass, const float* margin, const float* img, const float* txt, const float* cr,
    const float*& A, const float*& Bm, const float*& iA, const float*& iB,
    const float*& dg, const float*& mg) {
    switch (pass) {
        case 0: A = img; Bm = txt; iA = g_inva; iB = g_invt; dg = g_sm;   mg = margin; break;
        case 1: A = txt; Bm = img; iA = g_invt; iB = g_inva; dg = g_sm;   mg = margin; break;
        case 2: A = img; Bm = cr;  iA = g_inva; iB = g_invc; dg = g_smcr; mg = g_mcr;  break;
        default:A = cr;  Bm = img; iA = g_invc; iB = g_inva; dg = g_smcr; mg = g_mcr;  break;
    }
}

// -------- kernel 1: norms, diag sims, margin_cr, state reset (no writes of vecs)
__global__ __launch_bounds__(256) void prep_kernel(
    const float* __restrict__ img, const float* __restrict__ txt,
    const float* __restrict__ cr, const float* __restrict__ margin,
    const int* __restrict__ aflag) {
    int row = blockIdx.x * 8 + (threadIdx.x >> 5);
    int lane = threadIdx.x & 31;
    const float4* pi = (const float4*)(img + (size_t)row * DD);
    const float4* pt = (const float4*)(txt + (size_t)row * DD);
    const float4* pc = (const float4*)(cr + (size_t)row * DD);

    float sii = 0.f, stt = 0.f, scc = 0.f, sit = 0.f, sic = 0.f;
#pragma unroll
    for (int e = 0; e < 4; e++) {
        float4 vi = pi[lane + 32 * e];
        float4 vt = pt[lane + 32 * e];
        float4 vc = pc[lane + 32 * e];
        sii += vi.x * vi.x + vi.y * vi.y + vi.z * vi.z + vi.w * vi.w;
        stt += vt.x * vt.x + vt.y * vt.y + vt.z * vt.z + vt.w * vt.w;
        scc += vc.x * vc.x + vc.y * vc.y + vc.z * vc.z + vc.w * vc.w;
        sit += vi.x * vt.x + vi.y * vt.y + vi.z * vt.z + vi.w * vt.w;
        sic += vi.x * vc.x + vi.y * vc.y + vi.z * vc.z + vi.w * vc.w;
    }
#pragma unroll
    for (int off = 16; off; off >>= 1) {
        sii += __shfl_xor_sync(0xFFFFFFFFu, sii, off);
        stt += __shfl_xor_sync(0xFFFFFFFFu, stt, off);
        scc += __shfl_xor_sync(0xFFFFFFFFu, scc, off);
        sit += __shfl_xor_sync(0xFFFFFFFFu, sit, off);
        sic += __shfl_xor_sync(0xFFFFFFFFu, sic, off);
    }
    if (lane == 0) {
        float inva = 1.f / (sqrtf(sii) + 1e-8f);
        float invt = 1.f / (sqrtf(stt) + 1e-8f);
        float invc = 1.f / (sqrtf(scc) + 1e-8f);
        g_inva[row] = inva; g_invt[row] = invt; g_invc[row] = invc;
        float sm = sit * inva * invt;
        float smcr = sic * inva * invc;
        g_sm[row] = sm;
        g_smcr[row] = smcr;
        float mrg = margin[row];
        float mcr;
        if (*aflag) {
            float lam = fminf(fabsf(smcr) / fabsf(sm), 1.f);
            mcr = (lam + 1.f) * mrg * 0.5f;
        } else {
            mcr = mrg * 0.5f;
        }
        g_mcr[row] = mcr;
#pragma unroll
        for (int p = 0; p < 4; p++) g_best[p][row] = ~0ull;
    }
    if (blockIdx.x == 0 && threadIdx.x < 4) g_cnt[threadIdx.x] = 0;
}

// -------- kernel 2: phase-1 128x128 strip GEMM (f32x2) + mining -------------
__global__ __launch_bounds__(256, 2) void phase1_kernel(
    const float* __restrict__ img, const float* __restrict__ txt,
    const float* __restrict__ cr, const float* __restrict__ margin,
    const int* __restrict__ labels) {
    __shared__ __align__(16) float As[BK * P1];
    __shared__ __align__(16) float Bs[BK * P1];
    __shared__ unsigned long long sbest[BM];

    int pass = blockIdx.y;
    const float *A, *Bm, *iA, *iB, *dg, *mg;
    pass_ptrs(pass, margin, img, txt, cr, A, Bm, iA, iB, dg, mg);

    int rowStart = blockIdx.x * BM;
    int tid = threadIdx.x;
    int tx = tid & 15, ty = tid >> 4;

    if (tid < BM) sbest[tid] = ~0ull;

    unsigned long long acc[8][4];
#pragma unroll
    for (int i = 0; i < 8; i++)
#pragma unroll
        for (int j = 0; j < 4; j++) acc[i][j] = 0ull;

    int r0 = tid >> 2;
    int kk = (tid & 3) << 2;

    float iA0 = iA[rowStart + r0];
    float iA1 = iA[rowStart + r0 + 64];
    float iB0 = iB[r0];
    float iB1 = iB[r0 + 64];

    float4 pa0, pa1, pb0, pb1;
    pa0 = *(const float4*)&A[(size_t)(rowStart + r0) * DD + kk];
    pa1 = *(const float4*)&A[(size_t)(rowStart + r0 + 64) * DD + kk];
    pb0 = *(const float4*)&Bm[(size_t)r0 * DD + kk];
    pb1 = *(const float4*)&Bm[(size_t)(r0 + 64) * DD + kk];

    for (int k0 = 0; k0 < DD; k0 += BK) {
        __syncthreads();
        As[(kk + 0) * P1 + r0] = pa0.x * iA0; As[(kk + 1) * P1 + r0] = pa0.y * iA0;
        As[(kk + 2) * P1 + r0] = pa0.z * iA0; As[(kk + 3) * P1 + r0] = pa0.w * iA0;
        As[(kk + 0) * P1 + r0 + 64] = pa1.x * iA1; As[(kk + 1) * P1 + r0 + 64] = pa1.y * iA1;
        As[(kk + 2) * P1 + r0 + 64] = pa1.z * iA1; As[(kk + 3) * P1 + r0 + 64] = pa1.w * iA1;
        Bs[(kk + 0) * P1 + r0] = pb0.x * iB0; Bs[(kk + 1) * P1 + r0] = pb0.y * iB0;
        Bs[(kk + 2) * P1 + r0] = pb0.z * iB0; Bs[(kk + 3) * P1 + r0] = pb0.w * iB0;
        Bs[(kk + 0) * P1 + r0 + 64] = pb1.x * iB1; Bs[(kk + 1) * P1 + r0 + 64] = pb1.y * iB1;
        Bs[(kk + 2) * P1 + r0 + 64] = pb1.z * iB1; Bs[(kk + 3) * P1 + r0 + 64] = pb1.w * iB1;
        __syncthreads();

        if (k0 + BK < DD) {
            int kn = k0 + BK + kk;
            pa0 = *(const float4*)&A[(size_t)(rowStart + r0) * DD + kn];
            pa1 = *(const float4*)&A[(size_t)(rowStart + r0 + 64) * DD + kn];
            pb0 = *(const float4*)&Bm[(size_t)r0 * DD + kn];
            pb1 = *(const float4*)&Bm[(size_t)(r0 + 64) * DD + kn];
        }

#pragma unroll
        for (int k = 0; k < BK; k++) {
            float4 a0 = *(const float4*)&As[k * P1 + (ty << 2)];
            float4 a1 = *(const float4*)&As[k * P1 + 64 + (ty << 2)];
            ulonglong2 b0 = *(const ulonglong2*)&Bs[k * P1 + (tx << 2)];
            ulonglong2 b1 = *(const ulonglong2*)&Bs[k * P1 + 64 + (tx << 2)];
            float af[8] = {a0.x, a0.y, a0.z, a0.w, a1.x, a1.y, a1.z, a1.w};
#pragma unroll
            for (int i = 0; i < 8; i++) {
                unsigned long long aa;
                asm("mov.b64 %0, {%1, %1};" : "=l"(aa) : "f"(af[i]));
                asm("fma.rn.f32x2 %0, %1, %2, %0;" : "+l"(acc[i][0]) : "l"(aa), "l"(b0.x));
                asm("fma.rn.f32x2 %0, %1, %2, %0;" : "+l"(acc[i][1]) : "l"(aa), "l"(b0.y));
                asm("fma.rn.f32x2 %0, %1, %2, %0;" : "+l"(acc[i][2]) : "l"(aa), "l"(b1.x));
                asm("fma.rn.f32x2 %0, %1, %2, %0;" : "+l"(acc[i][3]) : "l"(aa), "l"(b1.y));
            }
        }
    }

    int lc[8];
#pragma unroll
    for (int jp = 0; jp < 4; jp++) {
        int cb = ((jp >> 1) ? 64 : 0) + (tx << 2) + ((jp & 1) << 1);
        lc[jp * 2 + 0] = labels[cb + 0];
        lc[jp * 2 + 1] = labels[cb + 1];
    }

#pragma unroll
    for (int i = 0; i < 8; i++) {
        int lrow = (i < 4) ? ((ty << 2) + i) : (64 + (ty << 2) + (i - 4));
        int arow = rowStart + lrow;
        float d = dg[arow];
        float m = mg[arow];
        int la = labels[arow];
        unsigned long long best = ~0ull;
#pragma unroll
        for (int jp = 0; jp < 4; jp++) {
            float lo, hi;
            asm("mov.b64 {%0, %1}, %2;" : "=f"(lo), "=f"(hi) : "l"(acc[i][jp]));
            int cb = ((jp >> 1) ? 64 : 0) + (tx << 2) + ((jp & 1) << 1);
            float loss0 = lo - d + m;
            float loss1 = hi - d + m;
            if (loss0 > 0.f && loss0 < m && lc[jp * 2 + 0] != la) {
                unsigned long long key = ((unsigned long long)cb << 32) |
                                         (unsigned long long)__float_as_uint(loss0);
                best = umin64(best, key);
            }
            if (loss1 > 0.f && loss1 < m && lc[jp * 2 + 1] != la) {
                unsigned long long key = ((unsigned long long)(cb + 1) << 32) |
                                         (unsigned long long)__float_as_uint(loss1);
                best = umin64(best, key);
            }
        }
        if (best != ~0ull) atomicMin(&sbest[lrow], best);
    }
    __syncthreads();
    if (tid < BM && sbest[tid] != ~0ull)
        atomicMin(&g_best[pass][rowStart + tid], sbest[tid]);
}

// -------- kernel 3: gather unresolved anchors --------
__global__ __launch_bounds__(256) void collect_kernel(
    const float* __restrict__ margin, const int* __restrict__ aflag) {
    int a = blockIdx.x * 256 + threadIdx.x;
    int pass = blockIdx.y;
    int af = *aflag;
    bool okm;
    if (pass < 2) okm = af ? (margin[a] >= 0.16f) : true;
    else          okm = af ? (g_mcr[a] >= 0.16f) : true;
    if (okm && g_best[pass][a] == ~0ull) {
        int p = atomicAdd(&g_cnt[pass], 1);
        g_list[pass][p] = a;
    }
}

// -------- kernel 4: phase-2 gathered 64x128x512 GEMM, prefetched ------------
__global__ __launch_bounds__(256) void phase2_kernel(
    const float* __restrict__ img, const float* __restrict__ txt,
    const float* __restrict__ cr, const float* __restrict__ margin,
    const int* __restrict__ labels) {
    __shared__ __align__(16) float As[BK * P2A];
    __shared__ __align__(16) float Bs[BK * P1];
    __shared__ int sList[64];
    __shared__ unsigned long long sbest[64];

    int pass = blockIdx.y;
    const float *A, *Bm, *iA, *iB, *dg, *mg;
    pass_ptrs(pass, margin, img, txt, cr, A, Bm, iA, iB, dg, mg);
    int cnt = g_cnt[pass];

    int colStart = W1 + blockIdx.x * BN;
    int tid = threadIdx.x;
    int tx = tid & 15, ty = tid >> 4;
    int r0 = tid >> 2;
    int kk = (tid & 3) << 2;

    float iB0 = iB[colStart + r0];
    float iB1 = iB[colStart + r0 + 64];
    const float* bRow0 = Bm + (size_t)(colStart + r0) * DD + kk;
    const float* bRow1 = Bm + (size_t)(colStart + r0 + 64) * DD + kk;

    for (int base = 0; base < cnt; base += 64) {
        __syncthreads();   // protect smem reuse across row-blocks
        if (tid < 64) {
            int idx = base + tid;
            sList[tid] = (idx < cnt) ? g_list[pass][idx] : g_list[pass][0];
            sbest[tid] = ~0ull;
        }
        __syncthreads();

        unsigned long long acc[4][4];
#pragma unroll
        for (int i = 0; i < 4; i++)
#pragma unroll
            for (int j = 0; j < 4; j++) acc[i][j] = 0ull;

        int arowr = sList[r0];
        float iA0 = iA[arowr];
        const float* aRowPtr = A + (size_t)arowr * DD + kk;

        float4 va = *(const float4*)(aRowPtr);
        float4 vb0 = *(const float4*)(bRow0);
        float4 vb1 = *(const float4*)(bRow1);

        for (int k0 = 0; k0 < DD; k0 += BK) {
            __syncthreads();
            As[(kk + 0) * P2A + r0] = va.x * iA0; As[(kk + 1) * P2A + r0] = va.y * iA0;
            As[(kk + 2) * P2A + r0] = va.z * iA0; As[(kk + 3) * P2A + r0] = va.w * iA0;
            Bs[(kk + 0) * P1 + r0] = vb0.x * iB0; Bs[(kk + 1) * P1 + r0] = vb0.y * iB0;
            Bs[(kk + 2) * P1 + r0] = vb0.z * iB0; Bs[(kk + 3) * P1 + r0] = vb0.w * iB0;
            Bs[(kk + 0) * P1 + r0 + 64] = vb1.x * iB1; Bs[(kk + 1) * P1 + r0 + 64] = vb1.y * iB1;
            Bs[(kk + 2) * P1 + r0 + 64] = vb1.z * iB1; Bs[(kk + 3) * P1 + r0 + 64] = vb1.w * iB1;
            __syncthreads();

            if (k0 + BK < DD) {
                int kn = k0 + BK;
                va = *(const float4*)(aRowPtr + kn);
                vb0 = *(const float4*)(bRow0 + kn);
                vb1 = *(const float4*)(bRow1 + kn);
            }

#pragma unroll
            for (int k = 0; k < BK; k++) {
                float4 a0 = *(const float4*)&As[k * P2A + (ty << 2)];
                ulonglong2 b0 = *(const ulonglong2*)&Bs[k * P1 + (tx << 2)];
                ulonglong2 b1 = *(const ulonglong2*)&Bs[k * P1 + 64 + (tx << 2)];
                float af[4] = {a0.x, a0.y, a0.z, a0.w};
#pragma unroll
                for (int i = 0; i < 4; i++) {
                    unsigned long long aa;
                    asm("mov.b64 %0, {%1, %1};" : "=l"(aa) : "f"(af[i]));
                    asm("fma.rn.f32x2 %0, %1, %2, %0;" : "+l"(acc[i][0]) : "l"(aa), "l"(b0.x));
                    asm("fma.rn.f32x2 %0, %1, %2, %0;" : "+l"(acc[i][1]) : "l"(aa), "l"(b0.y));
                    asm("fma.rn.f32x2 %0, %1, %2, %0;" : "+l"(acc[i][2]) : "l"(aa), "l"(b1.x));
                    asm("fma.rn.f32x2 %0, %1, %2, %0;" : "+l"(acc[i][3]) : "l"(aa), "l"(b1.y));
                }
            }
        }

        // mining epilogue
#pragma unroll
        for (int i = 0; i < 4; i++) {
            int lr = (ty << 2) + i;
            if (base + lr >= cnt) continue;
            int arow = sList[lr];
            float d = dg[arow];
            float m = mg[arow];
            int la = labels[arow];
            unsigned long long best = ~0ull;
#pragma unroll
            for (int jp = 0; jp < 4; jp++) {
                float lo, hi;
                asm("mov.b64 {%0, %1}, %2;" : "=f"(lo), "=f"(hi) : "l"(acc[i][jp]));
                int cb = colStart + ((jp >> 1) ? 64 : 0) + (tx << 2) + ((jp & 1) << 1);
                float loss0 = lo - d + m;
                float loss1 = hi - d + m;
                if (loss0 > 0.f && loss0 < m && labels[cb] != la) {
                    unsigned long long key = ((unsigned long long)cb << 32) |
                                             (unsigned long long)__float_as_uint(loss0);
                    best = umin64(best, key);
                }
                if (loss1 > 0.f && loss1 < m && labels[cb + 1] != la) {
                    unsigned long long key = ((unsigned long long)(cb + 1) << 32) |
                                             (unsigned long long)__float_as_uint(loss1);
                    best = umin64(best, key);
                }
            }
            if (best != ~0ull) atomicMin(&sbest[lr], best);
        }
        __syncthreads();
        if (tid < 64 && base + tid < cnt && sbest[tid] != ~0ull)
            atomicMin(&g_best[pass][sList[tid]], sbest[tid]);
    }
}

// -------- kernel 5: final reduction --------
__global__ __launch_bounds__(256) void final_kernel(
    const float* __restrict__ margin, const int* __restrict__ aflag,
    const float* __restrict__ crbeta, float* __restrict__ out) {
    __shared__ double sh1[256], sh2[256];
    int tid = threadIdx.x;
    int af = *aflag;
    double s1 = 0.0, s2 = 0.0;
    for (int a = tid; a < BB; a += 256) {
        bool okb = af ? (margin[a] >= 0.16f) : true;
        bool okc = af ? (g_mcr[a] >= 0.16f) : true;
        unsigned long long v;
        v = g_best[0][a];
        if (okb && v != ~0ull) s1 += (double)__uint_as_float((unsigned)v);
        v = g_best[1][a];
        if (okb && v != ~0ull) s1 += (double)__uint_as_float((unsigned)v);
        v = g_best[2][a];
        if (okc && v != ~0ull) s2 += (double)__uint_as_float((unsigned)v);
        v = g_best[3][a];
        if (okc && v != ~0ull) s2 += (double)__uint_as_float((unsigned)v);
    }
    sh1[tid] = s1; sh2[tid] = s2;
    __syncthreads();
    for (int s = 128; s; s >>= 1) {
        if (tid < s) { sh1[tid] += sh1[tid + s]; sh2[tid] += sh2[tid + s]; }
        __syncthreads();
    }
    if (tid == 0) out[0] = (float)(sh1[0] + (double)crbeta[0] * sh2[0]);
}

extern "C" void kernel_launch(void* const* d_in, const int* in_sizes, int n_in,
                              void* d_out, int out_size) {
    const float* img    = (const float*)d_in[0];
    const float* txt    = (const float*)d_in[1];
    const float* txtcr  = (const float*)d_in[2];
    const int*   labels = (const int*)d_in[3];
    const int*   aflag  = (const int*)d_in[4];
    const float* margin = (const float*)d_in[5];
    const float* crbeta = (const float*)d_in[6];
    float* out = (float*)d_out;

    prep_kernel<<<BB / 8, 256>>>(img, txt, txtcr, margin, aflag);
    phase1_kernel<<<dim3(BB / BM, 4), 256>>>(img, txt, txtcr, margin, labels);
    collect_kernel<<<dim3(BB / 256, 4), 256>>>(margin, aflag);
    phase2_kernel<<<dim3((BB - W1) / BN, 4), 256>>>(img, txt, txtcr, margin, labels);
    final_kernel<<<1, 256>>>(margin, aflag, crbeta, out);
}

// round 5
// speedup vs baseline: 2.3361x; 1.0640x over previous
#include <cuda_runtime.h>
#include <cuda_bf16.h>

#define BB 8192
#define DD 512
#define W1 128          // phase-1 candidate window
#define BM 128
#define BN 128
#define BK 16
#define NCH (DD / BK)   // 32 k-chunks
#define P1 132          // padded smem row (floats)
#define P2A 68          // phase2 A smem pad

// -------- scratch (device globals; no allocation allowed) --------
__device__ float g_inva[BB];
__device__ float g_invt[BB];
__device__ float g_invc[BB];
__device__ float g_sm[BB];
__device__ float g_smcr[BB];
__device__ float g_mcr[BB];
__device__ unsigned long long g_best[4][BB];
__device__ int g_cnt[4];
__device__ int g_list[4][BB];

static __device__ __forceinline__ unsigned long long umin64(unsigned long long a,
                                                            unsigned long long b) {
    return a < b ? a : b;
}

static __device__ __forceinline__ void pass_ptrs(
    int pass, const float* margin, const float* img, const float* txt, const float* cr,
    const float*& A, const float*& Bm, const float*& iA, const float*& iB,
    const float*& dg, const float*& mg) {
    switch (pass) {
        case 0: A = img; Bm = txt; iA = g_inva; iB = g_invt; dg = g_sm;   mg = margin; break;
        case 1: A = txt; Bm = img; iA = g_invt; iB = g_inva; dg = g_sm;   mg = margin; break;
        case 2: A = img; Bm = cr;  iA = g_inva; iB = g_invc; dg = g_smcr; mg = g_mcr;  break;
        default:A = cr;  Bm = img; iA = g_invc; iB = g_inva; dg = g_smcr; mg = g_mcr;  break;
    }
}

// -------- kernel 1: norms, diag sims, margin_cr, state reset ----------------
__global__ __launch_bounds__(256) void prep_kernel(
    const float* __restrict__ img, const float* __restrict__ txt,
    const float* __restrict__ cr, const float* __restrict__ margin,
    const int* __restrict__ aflag) {
    int row = blockIdx.x * 8 + (threadIdx.x >> 5);
    int lane = threadIdx.x & 31;
    const float4* pi = (const float4*)(img + (size_t)row * DD);
    const float4* pt = (const float4*)(txt + (size_t)row * DD);
    const float4* pc = (const float4*)(cr + (size_t)row * DD);

    float sii = 0.f, stt = 0.f, scc = 0.f, sit = 0.f, sic = 0.f;
#pragma unroll
    for (int e = 0; e < 4; e++) {
        float4 vi = pi[lane + 32 * e];
        float4 vt = pt[lane + 32 * e];
        float4 vc = pc[lane + 32 * e];
        sii += vi.x * vi.x + vi.y * vi.y + vi.z * vi.z + vi.w * vi.w;
        stt += vt.x * vt.x + vt.y * vt.y + vt.z * vt.z + vt.w * vt.w;
        scc += vc.x * vc.x + vc.y * vc.y + vc.z * vc.z + vc.w * vc.w;
        sit += vi.x * vt.x + vi.y * vt.y + vi.z * vt.z + vi.w * vt.w;
        sic += vi.x * vc.x + vi.y * vc.y + vi.z * vc.z + vi.w * vc.w;
    }
#pragma unroll
    for (int off = 16; off; off >>= 1) {
        sii += __shfl_xor_sync(0xFFFFFFFFu, sii, off);
        stt += __shfl_xor_sync(0xFFFFFFFFu, stt, off);
        scc += __shfl_xor_sync(0xFFFFFFFFu, scc, off);
        sit += __shfl_xor_sync(0xFFFFFFFFu, sit, off);
        sic += __shfl_xor_sync(0xFFFFFFFFu, sic, off);
    }
    if (lane == 0) {
        float inva = 1.f / (sqrtf(sii) + 1e-8f);
        float invt = 1.f / (sqrtf(stt) + 1e-8f);
        float invc = 1.f / (sqrtf(scc) + 1e-8f);
        g_inva[row] = inva; g_invt[row] = invt; g_invc[row] = invc;
        float sm = sit * inva * invt;
        float smcr = sic * inva * invc;
        g_sm[row] = sm;
        g_smcr[row] = smcr;
        float mrg = margin[row];
        float mcr;
        if (*aflag) {
            float lam = fminf(fabsf(smcr) / fabsf(sm), 1.f);
            mcr = (lam + 1.f) * mrg * 0.5f;
        } else {
            mcr = mrg * 0.5f;
        }
        g_mcr[row] = mcr;
#pragma unroll
        for (int p = 0; p < 4; p++) g_best[p][row] = ~0ull;
    }
    if (blockIdx.x == 0 && threadIdx.x < 4) g_cnt[threadIdx.x] = 0;
}

// inner-product microkernel step: 8 a-values x 4 f32x2 b-pairs
static __device__ __forceinline__ void mma8x8(
    unsigned long long acc[8][4], const float af[8],
    unsigned long long bx0, unsigned long long bx1,
    unsigned long long bx2, unsigned long long bx3) {
#pragma unroll
    for (int i = 0; i < 8; i++) {
        unsigned long long aa;
        asm("mov.b64 %0, {%1, %1};" : "=l"(aa) : "f"(af[i]));
        asm("fma.rn.f32x2 %0, %1, %2, %0;" : "+l"(acc[i][0]) : "l"(aa), "l"(bx0));
        asm("fma.rn.f32x2 %0, %1, %2, %0;" : "+l"(acc[i][1]) : "l"(aa), "l"(bx1));
        asm("fma.rn.f32x2 %0, %1, %2, %0;" : "+l"(acc[i][2]) : "l"(aa), "l"(bx2));
        asm("fma.rn.f32x2 %0, %1, %2, %0;" : "+l"(acc[i][3]) : "l"(aa), "l"(bx3));
    }
}

// -------- kernel 2: phase-1 128x128 strip GEMM, double-buffered -------------
__global__ __launch_bounds__(256, 2) void phase1_kernel(
    const float* __restrict__ img, const float* __restrict__ txt,
    const float* __restrict__ cr, const float* __restrict__ margin,
    const int* __restrict__ labels) {
    __shared__ __align__(16) float As[2][BK * P1];
    __shared__ __align__(16) float Bs[2][BK * P1];
    __shared__ unsigned long long sbest[BM];

    int pass = blockIdx.y;
    const float *A, *Bm, *iA, *iB, *dg, *mg;
    pass_ptrs(pass, margin, img, txt, cr, A, Bm, iA, iB, dg, mg);

    int rowStart = blockIdx.x * BM;
    int tid = threadIdx.x;
    int tx = tid & 15, ty = tid >> 4;

    if (tid < BM) sbest[tid] = ~0ull;

    unsigned long long acc[8][4];
#pragma unroll
    for (int i = 0; i < 8; i++)
#pragma unroll
        for (int j = 0; j < 4; j++) acc[i][j] = 0ull;

    int r0 = tid >> 2;
    int kk = (tid & 3) << 2;

    float iA0 = iA[rowStart + r0];
    float iA1 = iA[rowStart + r0 + 64];
    float iB0 = iB[r0];
    float iB1 = iB[r0 + 64];
    const float* aRow0 = A + (size_t)(rowStart + r0) * DD + kk;
    const float* aRow1 = A + (size_t)(rowStart + r0 + 64) * DD + kk;
    const float* bRow0 = Bm + (size_t)r0 * DD + kk;
    const float* bRow1 = Bm + (size_t)(r0 + 64) * DD + kk;

    float4 pa0 = *(const float4*)aRow0;
    float4 pa1 = *(const float4*)aRow1;
    float4 pb0 = *(const float4*)bRow0;
    float4 pb1 = *(const float4*)bRow1;

    // stage chunk 0 into buffer 0
    {
        float* as = As[0]; float* bs = Bs[0];
        as[(kk + 0) * P1 + r0] = pa0.x * iA0; as[(kk + 1) * P1 + r0] = pa0.y * iA0;
        as[(kk + 2) * P1 + r0] = pa0.z * iA0; as[(kk + 3) * P1 + r0] = pa0.w * iA0;
        as[(kk + 0) * P1 + r0 + 64] = pa1.x * iA1; as[(kk + 1) * P1 + r0 + 64] = pa1.y * iA1;
        as[(kk + 2) * P1 + r0 + 64] = pa1.z * iA1; as[(kk + 3) * P1 + r0 + 64] = pa1.w * iA1;
        bs[(kk + 0) * P1 + r0] = pb0.x * iB0; bs[(kk + 1) * P1 + r0] = pb0.y * iB0;
        bs[(kk + 2) * P1 + r0] = pb0.z * iB0; bs[(kk + 3) * P1 + r0] = pb0.w * iB0;
        bs[(kk + 0) * P1 + r0 + 64] = pb1.x * iB1; bs[(kk + 1) * P1 + r0 + 64] = pb1.y * iB1;
        bs[(kk + 2) * P1 + r0 + 64] = pb1.z * iB1; bs[(kk + 3) * P1 + r0 + 64] = pb1.w * iB1;
    }
    __syncthreads();

    for (int c = 0; c < NCH; c++) {
        int cur = c & 1;
        bool more = (c + 1 < NCH);
        if (more) {
            int kn = (c + 1) * BK;
            pa0 = *(const float4*)(aRow0 + kn);
            pa1 = *(const float4*)(aRow1 + kn);
            pb0 = *(const float4*)(bRow0 + kn);
            pb1 = *(const float4*)(bRow1 + kn);
        }
        const float* as = As[cur];
        const float* bs = Bs[cur];
#pragma unroll
        for (int k = 0; k < BK; k++) {
            float4 a0 = *(const float4*)&as[k * P1 + (ty << 2)];
            float4 a1 = *(const float4*)&as[k * P1 + 64 + (ty << 2)];
            ulonglong2 b0 = *(const ulonglong2*)&bs[k * P1 + (tx << 2)];
            ulonglong2 b1 = *(const ulonglong2*)&bs[k * P1 + 64 + (tx << 2)];
            float af[8] = {a0.x, a0.y, a0.z, a0.w, a1.x, a1.y, a1.z, a1.w};
            mma8x8(acc, af, b0.x, b0.y, b1.x, b1.y);
        }
        if (more) {
            float* asn = As[cur ^ 1]; float* bsn = Bs[cur ^ 1];
            asn[(kk + 0) * P1 + r0] = pa0.x * iA0; asn[(kk + 1) * P1 + r0] = pa0.y * iA0;
            asn[(kk + 2) * P1 + r0] = pa0.z * iA0; asn[(kk + 3) * P1 + r0] = pa0.w * iA0;
            asn[(kk + 0) * P1 + r0 + 64] = pa1.x * iA1; asn[(kk + 1) * P1 + r0 + 64] = pa1.y * iA1;
            asn[(kk + 2) * P1 + r0 + 64] = pa1.z * iA1; asn[(kk + 3) * P1 + r0 + 64] = pa1.w * iA1;
            bsn[(kk + 0) * P1 + r0] = pb0.x * iB0; bsn[(kk + 1) * P1 + r0] = pb0.y * iB0;
            bsn[(kk + 2) * P1 + r0] = pb0.z * iB0; bsn[(kk + 3) * P1 + r0] = pb0.w * iB0;
            bsn[(kk + 0) * P1 + r0 + 64] = pb1.x * iB1; bsn[(kk + 1) * P1 + r0 + 64] = pb1.y * iB1;
            bsn[(kk + 2) * P1 + r0 + 64] = pb1.z * iB1; bsn[(kk + 3) * P1 + r0 + 64] = pb1.w * iB1;
        }
        __syncthreads();
    }

    int lc[8];
#pragma unroll
    for (int jp = 0; jp < 4; jp++) {
        int cb = ((jp >> 1) ? 64 : 0) + (tx << 2) + ((jp & 1) << 1);
        lc[jp * 2 + 0] = labels[cb + 0];
        lc[jp * 2 + 1] = labels[cb + 1];
    }

#pragma unroll
    for (int i = 0; i < 8; i++) {
        int lrow = (i < 4) ? ((ty << 2) + i) : (64 + (ty << 2) + (i - 4));
        int arow = rowStart + lrow;
        float d = dg[arow];
        float m = mg[arow];
        int la = labels[arow];
        unsigned long long best = ~0ull;
#pragma unroll
        for (int jp = 0; jp < 4; jp++) {
            float lo, hi;
            asm("mov.b64 {%0, %1}, %2;" : "=f"(lo), "=f"(hi) : "l"(acc[i][jp]));
            int cb = ((jp >> 1) ? 64 : 0) + (tx << 2) + ((jp & 1) << 1);
            float loss0 = lo - d + m;
            float loss1 = hi - d + m;
            if (loss0 > 0.f && loss0 < m && lc[jp * 2 + 0] != la) {
                unsigned long long key = ((unsigned long long)cb << 32) |
                                         (unsigned long long)__float_as_uint(loss0);
                best = umin64(best, key);
            }
            if (loss1 > 0.f && loss1 < m && lc[jp * 2 + 1] != la) {
                unsigned long long key = ((unsigned long long)(cb + 1) << 32) |
                                         (unsigned long long)__float_as_uint(loss1);
                best = umin64(best, key);
            }
        }
        if (best != ~0ull) atomicMin(&sbest[lrow], best);
    }
    __syncthreads();
    if (tid < BM && sbest[tid] != ~0ull)
        atomicMin(&g_best[pass][rowStart + tid], sbest[tid]);
}

// -------- kernel 3: gather unresolved anchors --------
__global__ __launch_bounds__(256) void collect_kernel(
    const float* __restrict__ margin, const int* __restrict__ aflag) {
    int a = blockIdx.x * 256 + threadIdx.x;
    int pass = blockIdx.y;
    int af = *aflag;
    bool okm;
    if (pass < 2) okm = af ? (margin[a] >= 0.16f) : true;
    else          okm = af ? (g_mcr[a] >= 0.16f) : true;
    if (okm && g_best[pass][a] == ~0ull) {
        int p = atomicAdd(&g_cnt[pass], 1);
        g_list[pass][p] = a;
    }
}

// -------- kernel 4: phase-2 gathered 64x128 GEMM, 128 thr, 8x8 microtile ----
__global__ __launch_bounds__(128) void phase2_kernel(
    const float* __restrict__ img, const float* __restrict__ txt,
    const float* __restrict__ cr, const float* __restrict__ margin,
    const int* __restrict__ labels) {
    __shared__ __align__(16) float As[2][BK * P2A];
    __shared__ __align__(16) float Bs[2][BK * P1];
    __shared__ int sList[64];
    __shared__ unsigned long long sbest[64];

    int pass = blockIdx.y;
    const float *A, *Bm, *iA, *iB, *dg, *mg;
    pass_ptrs(pass, margin, img, txt, cr, A, Bm, iA, iB, dg, mg);
    int cnt = g_cnt[pass];

    int colStart = W1 + blockIdx.x * BN;
    int tid = threadIdx.x;
    int tx = tid & 15, ty = tid >> 4;          // 16 x 8
    int ar = tid >> 1;                          // 0..63
    int ak = (tid & 1) << 3;                    // 0 or 8

    float iB0 = iB[colStart + ar];
    float iB1 = iB[colStart + ar + 64];
    const float* bRow0 = Bm + (size_t)(colStart + ar) * DD + ak;
    const float* bRow1 = Bm + (size_t)(colStart + ar + 64) * DD + ak;

    for (int base = 0; base < cnt; base += 64) {
        __syncthreads();
        if (tid < 64) {
            int idx = base + tid;
            sList[tid] = (idx < cnt) ? g_list[pass][idx] : g_list[pass][0];
            sbest[tid] = ~0ull;
        }
        __syncthreads();

        unsigned long long acc[8][4];
#pragma unroll
        for (int i = 0; i < 8; i++)
#pragma unroll
            for (int j = 0; j < 4; j++) acc[i][j] = 0ull;

        int arowr = sList[ar];
        float iA0 = iA[arowr];
        const float* aRowPtr = A + (size_t)arowr * DD + ak;

        float4 va0 = *(const float4*)(aRowPtr);
        float4 va1 = *(const float4*)(aRowPtr + 4);
        float4 vb00 = *(const float4*)(bRow0);
        float4 vb01 = *(const float4*)(bRow0 + 4);
        float4 vb10 = *(const float4*)(bRow1);
        float4 vb11 = *(const float4*)(bRow1 + 4);

        // stage chunk 0 into buffer 0
        {
            float* as = As[0]; float* bs = Bs[0];
            as[(ak + 0) * P2A + ar] = va0.x * iA0; as[(ak + 1) * P2A + ar] = va0.y * iA0;
            as[(ak + 2) * P2A + ar] = va0.z * iA0; as[(ak + 3) * P2A + ar] = va0.w * iA0;
            as[(ak + 4) * P2A + ar] = va1.x * iA0; as[(ak + 5) * P2A + ar] = va1.y * iA0;
            as[(ak + 6) * P2A + ar] = va1.z * iA0; as[(ak + 7) * P2A + ar] = va1.w * iA0;
            bs[(ak + 0) * P1 + ar] = vb00.x * iB0; bs[(ak + 1) * P1 + ar] = vb00.y * iB0;
            bs[(ak + 2) * P1 + ar] = vb00.z * iB0; bs[(ak + 3) * P1 + ar] = vb00.w * iB0;
            bs[(ak + 4) * P1 + ar] = vb01.x * iB0; bs[(ak + 5) * P1 + ar] = vb01.y * iB0;
            bs[(ak + 6) * P1 + ar] = vb01.z * iB0; bs[(ak + 7) * P1 + ar] = vb01.w * iB0;
            bs[(ak + 0) * P1 + ar + 64] = vb10.x * iB1; bs[(ak + 1) * P1 + ar + 64] = vb10.y * iB1;
            bs[(ak + 2) * P1 + ar + 64] = vb10.z * iB1; bs[(ak + 3) * P1 + ar + 64] = vb10.w * iB1;
            bs[(ak + 4) * P1 + ar + 64] = vb11.x * iB1; bs[(ak + 5) * P1 + ar + 64] = vb11.y * iB1;
            bs[(ak + 6) * P1 + ar + 64] = vb11.z * iB1; bs[(ak + 7) * P1 + ar + 64] = vb11.w * iB1;
        }
        __syncthreads();

        for (int c = 0; c < NCH; c++) {
            int cur = c & 1;
            bool more = (c + 1 < NCH);
            if (more) {
                int kn = (c + 1) * BK;
                va0 = *(const float4*)(aRowPtr + kn);
                va1 = *(const float4*)(aRowPtr + kn + 4);
                vb00 = *(const float4*)(bRow0 + kn);
                vb01 = *(const float4*)(bRow0 + kn + 4);
                vb10 = *(const float4*)(bRow1 + kn);
                vb11 = *(const float4*)(bRow1 + kn + 4);
            }
            const float* as = As[cur];
            const float* bs = Bs[cur];
#pragma unroll
            for (int k = 0; k < BK; k++) {
                float4 a0 = *(const float4*)&as[k * P2A + (ty << 2)];
                float4 a1 = *(const float4*)&as[k * P2A + 32 + (ty << 2)];
                ulonglong2 b0 = *(const ulonglong2*)&bs[k * P1 + (tx << 2)];
                ulonglong2 b1 = *(const ulonglong2*)&bs[k * P1 + 64 + (tx << 2)];
                float af[8] = {a0.x, a0.y, a0.z, a0.w, a1.x, a1.y, a1.z, a1.w};
                mma8x8(acc, af, b0.x, b0.y, b1.x, b1.y);
            }
            if (more) {
                float* asn = As[cur ^ 1]; float* bsn = Bs[cur ^ 1];
                asn[(ak + 0) * P2A + ar] = va0.x * iA0; asn[(ak + 1) * P2A + ar] = va0.y * iA0;
                asn[(ak + 2) * P2A + ar] = va0.z * iA0; asn[(ak + 3) * P2A + ar] = va0.w * iA0;
                asn[(ak + 4) * P2A + ar] = va1.x * iA0; asn[(ak + 5) * P2A + ar] = va1.y * iA0;
                asn[(ak + 6) * P2A + ar] = va1.z * iA0; asn[(ak + 7) * P2A + ar] = va1.w * iA0;
                bsn[(ak + 0) * P1 + ar] = vb00.x * iB0; bsn[(ak + 1) * P1 + ar] = vb00.y * iB0;
                bsn[(ak + 2) * P1 + ar] = vb00.z * iB0; bsn[(ak + 3) * P1 + ar] = vb00.w * iB0;
                bsn[(ak + 4) * P1 + ar] = vb01.x * iB0; bsn[(ak + 5) * P1 + ar] = vb01.y * iB0;
                bsn[(ak + 6) * P1 + ar] = vb01.z * iB0; bsn[(ak + 7) * P1 + ar] = vb01.w * iB0;
                bsn[(ak + 0) * P1 + ar + 64] = vb10.x * iB1; bsn[(ak + 1) * P1 + ar + 64] = vb10.y * iB1;
                bsn[(ak + 2) * P1 + ar + 64] = vb10.z * iB1; bsn[(ak + 3) * P1 + ar + 64] = vb10.w * iB1;
                bsn[(ak + 4) * P1 + ar + 64] = vb11.x * iB1; bsn[(ak + 5) * P1 + ar + 64] = vb11.y * iB1;
                bsn[(ak + 6) * P1 + ar + 64] = vb11.z * iB1; bsn[(ak + 7) * P1 + ar + 64] = vb11.w * iB1;
            }
            __syncthreads();
        }

        // mining epilogue: 8 rows x 8 cols
#pragma unroll
        for (int i = 0; i < 8; i++) {
            int lr = (i < 4) ? ((ty << 2) + i) : (32 + (ty << 2) + (i - 4));
            if (base + lr >= cnt) continue;
            int arow = sList[lr];
            float d = dg[arow];
            float m = mg[arow];
            int la = labels[arow];
            unsigned long long best = ~0ull;
#pragma unroll
            for (int jp = 0; jp < 4; jp++) {
                float lo, hi;
                asm("mov.b64 {%0, %1}, %2;" : "=f"(lo), "=f"(hi) : "l"(acc[i][jp]));
                int cb = colStart + ((jp >> 1) ? 64 : 0) + (tx << 2) + ((jp & 1) << 1);
                float loss0 = lo - d + m;
                float loss1 = hi - d + m;
                if (loss0 > 0.f && loss0 < m && labels[cb] != la) {
                    unsigned long long key = ((unsigned long long)cb << 32) |
                                             (unsigned long long)__float_as_uint(loss0);
                    best = umin64(best, key);
                }
                if (loss1 > 0.f && loss1 < m && labels[cb + 1] != la) {
                    unsigned long long key = ((unsigned long long)(cb + 1) << 32) |
                                             (unsigned long long)__float_as_uint(loss1);
                    best = umin64(best, key);
                }
            }
            if (best != ~0ull) atomicMin(&sbest[lr], best);
        }
        __syncthreads();
        if (tid < 64 && base + tid < cnt && sbest[tid] != ~0ull)
            atomicMin(&g_best[pass][sList[tid]], sbest[tid]);
    }
}

// -------- kernel 5: final reduction --------
__global__ __launch_bounds__(256) void final_kernel(
    const float* __restrict__ margin, const int* __restrict__ aflag,
    const float* __restrict__ crbeta, float* __restrict__ out) {
    __shared__ double sh1[256], sh2[256];
    int tid = threadIdx.x;
    int af = *aflag;
    double s1 = 0.0, s2 = 0.0;
    for (int a = tid; a < BB; a += 256) {
        bool okb = af ? (margin[a] >= 0.16f) : true;
        bool okc = af ? (g_mcr[a] >= 0.16f) : true;
        unsigned long long v;
        v = g_best[0][a];
        if (okb && v != ~0ull) s1 += (double)__uint_as_float((unsigned)v);
        v = g_best[1][a];
        if (okb && v != ~0ull) s1 += (double)__uint_as_float((unsigned)v);
        v = g_best[2][a];
        if (okc && v != ~0ull) s2 += (double)__uint_as_float((unsigned)v);
        v = g_best[3][a];
        if (okc && v != ~0ull) s2 += (double)__uint_as_float((unsigned)v);
    }
    sh1[tid] = s1; sh2[tid] = s2;
    __syncthreads();
    for (int s = 128; s; s >>= 1) {
        if (tid < s) { sh1[tid] += sh1[tid + s]; sh2[tid] += sh2[tid + s]; }
        __syncthreads();
    }
    if (tid == 0) out[0] = (float)(sh1[0] + (double)crbeta[0] * sh2[0]);
}

extern "C" void kernel_launch(void* const* d_in, const int* in_sizes, int n_in,
                              void* d_out, int out_size) {
    const float* img    = (const float*)d_in[0];
    const float* txt    = (const float*)d_in[1];
    const float* txtcr  = (const float*)d_in[2];
    const int*   labels = (const int*)d_in[3];
    const int*   aflag  = (const int*)d_in[4];
    const float* margin = (const float*)d_in[5];
    const float* crbeta = (const float*)d_in[6];
    float* out = (float*)d_out;

    prep_kernel<<<BB / 8, 256>>>(img, txt, txtcr, margin, aflag);
    phase1_kernel<<<dim3(BB / BM, 4), 256>>>(img, txt, txtcr, margin, labels);
    collect_kernel<<<dim3(BB / 256, 4), 256>>>(margin, aflag);
    phase2_kernel<<<dim3((BB - W1) / BN, 4), 128>>>(img, txt, txtcr, margin, labels);
    final_kernel<<<1, 256>>>(margin, aflag, crbeta, out);
}